// round 12
// baseline (speedup 1.0000x reference)
#include <cuda_runtime.h>
#include <cuda_bf16.h>
#include <cstdint>

#define S_LEN 128
#define B_SZ  64
#define V_SZ  32000
#define E_SZ  32
#define H_SZ  16
#define NROWS (S_LEN * B_SZ)   // 8192

#define MT     128             // rows per tile (8 warps x 16 rows)
#define NMT    (NROWS / MT)    // 64 tiles
#define VSPLIT 16
#define VR     (V_SZ / VSPLIT) // 2000 cols per chunk
#define NG     (VR / 16)       // 125 col-groups
#define NWT2   (V_SZ * H_SZ / 2)
#define GENBLK 128             // blocks per generation (8 tiles)

#define LOG2E 1.4426950408889634f
#define LN2   0.6931471805599453f

// -------- device scratch (allocation-free rule) --------------------------------
__device__ float    g_xin[NROWS * H_SZ];
__device__ float    g_h[NROWS * H_SZ];
__device__ uint32_t g_wt2[NWT2];              // Wo in MMA-B-fragment layout
__device__ float    g_ps[NROWS * VSPLIT];     // partial sum(exp) per (row, chunk)
__device__ volatile int g_a0done;             // chunks of pass0 completed
__device__ volatile int g_tdone[NMT];         // per-tile pass0 chunk count

// -------- helpers ---------------------------------------------------------------
__device__ __forceinline__ uint32_t packbf(float lo, float hi) {
    __nv_bfloat162 p = __floats2bfloat162_rn(lo, hi);
    return *reinterpret_cast<uint32_t*>(&p);
}
__device__ __forceinline__ float ex2(float x) {
    float r;
    asm("ex2.approx.f32 %0, %1;" : "=f"(r) : "f"(x));
    return r;
}
__device__ __forceinline__ void mma16816(float d[4], const uint32_t a[4],
                                         uint32_t b0, uint32_t b1) {
    float z = 0.f;
    asm volatile(
        "mma.sync.aligned.m16n8k16.row.col.f32.bf16.bf16.f32 "
        "{%0,%1,%2,%3}, {%4,%5,%6,%7}, {%8,%9}, {%10,%11,%12,%13};"
        : "=f"(d[0]), "=f"(d[1]), "=f"(d[2]), "=f"(d[3])
        : "r"(a[0]), "r"(a[1]), "r"(a[2]), "r"(a[3]),
          "r"(b0), "r"(b1),
          "f"(z), "f"(z), "f"(z), "f"(z));
}

// -------- K0: xin = lookup[idx] @ Wx  (+ counter reset for this launch) ---------
__global__ void k_embed(const int* __restrict__ idx,
                        const float* __restrict__ lookup,
                        const float* __restrict__ wx) {
    if (blockIdx.x == 0 && threadIdx.x < NMT + 1) {
        if (threadIdx.x == 0) g_a0done = 0;
        else                  g_tdone[threadIdx.x - 1] = 0;
    }
    int t = blockIdx.x * blockDim.x + threadIdx.x;  // 32768 threads
    int row = t >> 2, j0 = (t & 3) * 4;
    const float* L = lookup + (long)idx[row] * E_SZ;
    float4 acc = make_float4(0.f, 0.f, 0.f, 0.f);
#pragma unroll
    for (int e = 0; e < E_SZ; e++) {
        float le = L[e];
        float4 w = *reinterpret_cast<const float4*>(wx + e * H_SZ + j0);
        acc.x += le * w.x; acc.y += le * w.y;
        acc.z += le * w.z; acc.w += le * w.w;
    }
    *reinterpret_cast<float4*>(g_xin + (long)row * H_SZ + j0) = acc;
}

// -------- K_prep: fused recurrence (blocks 0..31) + Wo repack (blocks 32..95) ---
__global__ void k_prep(const float* __restrict__ wh,
                       const float* __restrict__ h0,
                       const float* __restrict__ wo) {
    int blk = blockIdx.x;
    if (blk < 32) {
        int tid = threadIdx.x;
        if (tid >= 32) return;
        int half = tid >> 4;
        int j    = tid & 15;
        int bb   = blk * 2 + half;
        int base = bb * H_SZ + j;
        int src0 = half << 4;

        float whr[H_SZ];
#pragma unroll
        for (int k = 0; k < H_SZ; k++) whr[k] = wh[k * H_SZ + j];

        float h   = h0[base];
        float xin = g_xin[base];
        for (int s = 0; s < S_LEN; s++) {
            float nxt = (s + 1 < S_LEN) ? g_xin[(s + 1) * (B_SZ * H_SZ) + base] : 0.f;
            float acc = xin;
#pragma unroll
            for (int k = 0; k < H_SZ; k++) {
                float hk = __shfl_sync(0xffffffffu, h, src0 | k);
                acc += hk * whr[k];
            }
            // fast tanh via ex2 + fast division (rel err ~1e-6, << bf16 quant)
            float e = ex2(acc * (2.0f * LOG2E));
            h = __fdividef(e - 1.0f, e + 1.0f);
            g_h[s * (B_SZ * H_SZ) + base] = h;
            xin = nxt;
        }
    } else {
        int t0 = ((blk - 32) * 256 + threadIdx.x) * 16;
        if (t0 >= NWT2) return;
        uint32_t v[16];
#pragma unroll
        for (int i = 0; i < 16; i++) {
            int t = t0 + i;
            int g = t >> 7, rem = t & 127;
            int lane = rem >> 2, r = rem & 3;
            int tc   = lane >> 2;
            int tile = r >> 1;
            int col  = g * 16 + 2 * tc - (tc & 1) + 2 * tile;
            int k0   = (lane & 3) * 2 + (r & 1) * 8;
            v[i] = packbf(wo[k0 * V_SZ + col], wo[(k0 + 1) * V_SZ + col]);
        }
        uint4* dst = reinterpret_cast<uint4*>(g_wt2 + t0);
#pragma unroll
        for (int i = 0; i < 4; i++)
            dst[i] = make_uint4(v[4 * i], v[4 * i + 1], v[4 * i + 2], v[4 * i + 3]);
    }
}

// -------- K2 fused: generation-pipelined pass0 (sum exp) + pass1 (store) --------
// Linear grid 1024: tile T = blk>>4, chunk bx = blk&15, gen = blk>>7.
// Gen g's pass0 waits for gens <g pass0 -> overlaps their DRAM-bound pass1.
// Progress: all waits are on strictly lower block indices (in-order dispatch).
__global__ __launch_bounds__(256)
void k2f(float* __restrict__ out) {
    int blk  = blockIdx.x;
    int T    = blk >> 4;
    int bx   = blk & 15;
    int gen  = blk >> 7;
    int tid  = threadIdx.x;
    int w    = tid >> 5;
    int lane = tid & 31;
    int lq   = lane & 3;
    int m0   = T * MT;
    int wr0  = m0 + w * 16;
    int rA   = lane >> 2;
    int kc   = lq * 2;

    // A fragment, pre-scaled by log2(e): pass0 exp = ex2(d); pass1 logit = d*ln2
    const float* hA = g_h + (long)(wr0 + rA) * H_SZ;
    const float* hB = g_h + (long)(wr0 + rA + 8) * H_SZ;
    uint32_t a[4];
    a[0] = packbf(LOG2E * hA[kc],     LOG2E * hA[kc + 1]);
    a[1] = packbf(LOG2E * hB[kc],     LOG2E * hB[kc + 1]);
    a[2] = packbf(LOG2E * hA[kc + 8], LOG2E * hA[kc + 9]);
    a[3] = packbf(LOG2E * hB[kc + 8], LOG2E * hB[kc + 9]);

    const uint4* bptr = reinterpret_cast<const uint4*>(g_wt2) + (long)bx * NG * 32 + lane;
    long orowA = (long)(wr0 + rA) * V_SZ + bx * VR + 4 * lq;
    long orowB = orowA + 8L * V_SZ;

    // ---- generation gate: wait for all earlier gens' pass0 ----
    if (gen > 0) {
        if (tid == 0) {
            while (g_a0done < gen * GENBLK) __nanosleep(200);
        }
        __syncthreads();
    }

    // ---- pass 0: sum(exp) for chunk (bx, T) ----
    {
        float psA = 0.f, psB = 0.f;
#pragma unroll 5
        for (int g = 0; g < NG; g++) {
            uint4 b = bptr[(long)g * 32];
            float d0[4], d1[4];
            mma16816(d0, a, b.x, b.y);
            mma16816(d1, a, b.z, b.w);
            psA += ex2(d0[0]) + ex2(d0[1]) + ex2(d1[0]) + ex2(d1[1]);
            psB += ex2(d0[2]) + ex2(d0[3]) + ex2(d1[2]) + ex2(d1[3]);
        }
        psA += __shfl_xor_sync(0xffffffffu, psA, 1);
        psA += __shfl_xor_sync(0xffffffffu, psA, 2);
        psB += __shfl_xor_sync(0xffffffffu, psB, 1);
        psB += __shfl_xor_sync(0xffffffffu, psB, 2);
        if (lq == 0) {
            g_ps[(long)(wr0 + rA) * VSPLIT + bx]     = psA;
            g_ps[(long)(wr0 + rA + 8) * VSPLIT + bx] = psB;
        }
    }
    __threadfence();
    __syncthreads();
    if (tid == 0) {
        atomicAdd((int*)&g_tdone[T], 1);
        atomicAdd((int*)&g_a0done, 1);
    }

    // ---- pass 1 gate: all 16 chunks of tile T done (lane 0 of every warp spins;
    //      read-only poll, no single-warp scheduling dependence) ----
    if (lane == 0) {
        while (g_tdone[T] < 16) __nanosleep(100);
    }
    __syncthreads();
    __threadfence();

    // lse per row
    float lseA, lseB;
    {
        const float4* pp = reinterpret_cast<const float4*>(g_ps + (long)(wr0 + rA) * VSPLIT);
        const float4* qq = reinterpret_cast<const float4*>(g_ps + (long)(wr0 + rA + 8) * VSPLIT);
        float sa = 0.f, sb = 0.f;
#pragma unroll
        for (int i = 0; i < VSPLIT / 4; i++) {
            float4 p = pp[i], q = qq[i];
            sa += (p.x + p.y) + (p.z + p.w);
            sb += (q.x + q.y) + (q.z + q.w);
        }
        lseA = __logf(sa);
        lseB = __logf(sb);
    }

    // ---- pass 1: store logit - lse  (logit = d * ln2) ----
#pragma unroll 5
    for (int g = 0; g < NG; g++) {
        uint4 b = bptr[(long)g * 32];
        float d0[4], d1[4];
        mma16816(d0, a, b.x, b.y);
        mma16816(d1, a, b.z, b.w);
        float4 vA = make_float4(fmaf(d0[0], LN2, -lseA), fmaf(d0[1], LN2, -lseA),
                                fmaf(d1[0], LN2, -lseA), fmaf(d1[1], LN2, -lseA));
        float4 vB = make_float4(fmaf(d0[2], LN2, -lseB), fmaf(d0[3], LN2, -lseB),
                                fmaf(d1[2], LN2, -lseB), fmaf(d1[3], LN2, -lseB));
        *reinterpret_cast<float4*>(out + orowA + g * 16) = vA;
        *reinterpret_cast<float4*>(out + orowB + g * 16) = vB;
    }
}

// -------- launch ----------------------------------------------------------------
extern "C" void kernel_launch(void* const* d_in, const int* in_sizes, int n_in,
                              void* d_out, int out_size) {
    const int*   input_batch = (const int*)d_in[0];
    const float* lookup      = (const float*)d_in[1];
    const float* weight_x    = (const float*)d_in[2];
    const float* weight_h    = (const float*)d_in[3];
    const float* weight_o    = (const float*)d_in[4];
    const float* h0          = (const float*)d_in[5];
    float*       out         = (float*)d_out;

    k_embed<<<(NROWS * H_SZ / 4) / 256, 256>>>(input_batch, lookup, weight_x);
    k_prep<<<96, 256>>>(weight_h, h0, weight_o);
    k2f<<<VSPLIT * NMT, 256>>>(out);
}

// round 13
// speedup vs baseline: 1.7782x; 1.7782x over previous
#include <cuda_runtime.h>
#include <cuda_bf16.h>
#include <cstdint>

#define S_LEN 128
#define B_SZ  64
#define V_SZ  32000
#define E_SZ  32
#define H_SZ  16
#define NROWS (S_LEN * B_SZ)   // 8192

#define MT     128             // rows per tile (8 warps x 16 rows)
#define NMT    (NROWS / MT)    // 64 tiles
#define VSPLIT 16
#define VR     (V_SZ / VSPLIT) // 2000 cols per chunk
#define NG     (VR / 16)       // 125 col-groups
#define NWT2   (V_SZ * H_SZ / 2)

#define LOG2E 1.4426950408889634f
#define LN2   0.6931471805599453f

// -------- device scratch (allocation-free rule) --------------------------------
__device__ float    g_xin[NROWS * H_SZ];
__device__ float    g_h[NROWS * H_SZ];
__device__ uint32_t g_wt2[NWT2];              // Wo in MMA-B-fragment layout
__device__ float    g_ps[NROWS * VSPLIT];     // partial sum(exp) per (row, chunk)
__device__ volatile int g_tdone[NMT];         // per-tile pass0 chunk count

// -------- helpers ---------------------------------------------------------------
__device__ __forceinline__ uint32_t packbf(float lo, float hi) {
    __nv_bfloat162 p = __floats2bfloat162_rn(lo, hi);
    return *reinterpret_cast<uint32_t*>(&p);
}
__device__ __forceinline__ float ex2(float x) {
    float r;
    asm("ex2.approx.f32 %0, %1;" : "=f"(r) : "f"(x));
    return r;
}
__device__ __forceinline__ void mma16816(float d[4], const uint32_t a[4],
                                         uint32_t b0, uint32_t b1) {
    float z = 0.f;
    asm volatile(
        "mma.sync.aligned.m16n8k16.row.col.f32.bf16.bf16.f32 "
        "{%0,%1,%2,%3}, {%4,%5,%6,%7}, {%8,%9}, {%10,%11,%12,%13};"
        : "=f"(d[0]), "=f"(d[1]), "=f"(d[2]), "=f"(d[3])
        : "r"(a[0]), "r"(a[1]), "r"(a[2]), "r"(a[3]),
          "r"(b0), "r"(b1),
          "f"(z), "f"(z), "f"(z), "f"(z));
}

// -------- K0: xin = lookup[idx] @ Wx  (+ counter reset for this launch) ---------
__global__ void k_embed(const int* __restrict__ idx,
                        const float* __restrict__ lookup,
                        const float* __restrict__ wx) {
    if (blockIdx.x == 0 && threadIdx.x < NMT)
        g_tdone[threadIdx.x] = 0;
    int t = blockIdx.x * blockDim.x + threadIdx.x;  // 32768 threads
    int row = t >> 2, j0 = (t & 3) * 4;
    const float* L = lookup + (long)idx[row] * E_SZ;
    float4 acc = make_float4(0.f, 0.f, 0.f, 0.f);
#pragma unroll
    for (int e = 0; e < E_SZ; e++) {
        float le = L[e];
        float4 w = *reinterpret_cast<const float4*>(wx + e * H_SZ + j0);
        acc.x += le * w.x; acc.y += le * w.y;
        acc.z += le * w.z; acc.w += le * w.w;
    }
    *reinterpret_cast<float4*>(g_xin + (long)row * H_SZ + j0) = acc;
}

// -------- K_prep: fused recurrence (blocks 0..31) + Wo repack (blocks 32..95) ---
__global__ void k_prep(const float* __restrict__ wh,
                       const float* __restrict__ h0,
                       const float* __restrict__ wo) {
    int blk = blockIdx.x;
    if (blk < 32) {
        int tid = threadIdx.x;
        if (tid >= 32) return;
        int half = tid >> 4;
        int j    = tid & 15;
        int bb   = blk * 2 + half;
        int base = bb * H_SZ + j;
        int src0 = half << 4;

        float whr[H_SZ];
#pragma unroll
        for (int k = 0; k < H_SZ; k++) whr[k] = wh[k * H_SZ + j];

        float h   = h0[base];
        float xin = g_xin[base];
        for (int s = 0; s < S_LEN; s++) {
            float nxt = (s + 1 < S_LEN) ? g_xin[(s + 1) * (B_SZ * H_SZ) + base] : 0.f;
            float acc = xin;
#pragma unroll
            for (int k = 0; k < H_SZ; k++) {
                float hk = __shfl_sync(0xffffffffu, h, src0 | k);
                acc += hk * whr[k];
            }
            // fast tanh via ex2 + fast division (rel err ~1e-6, << bf16 quant)
            float e = ex2(acc * (2.0f * LOG2E));
            h = __fdividef(e - 1.0f, e + 1.0f);
            g_h[s * (B_SZ * H_SZ) + base] = h;
            xin = nxt;
        }
    } else {
        int t0 = ((blk - 32) * 256 + threadIdx.x) * 16;
        if (t0 >= NWT2) return;
        uint32_t v[16];
#pragma unroll
        for (int i = 0; i < 16; i++) {
            int t = t0 + i;
            int g = t >> 7, rem = t & 127;
            int lane = rem >> 2, r = rem & 3;
            int tc   = lane >> 2;
            int tile = r >> 1;
            int col  = g * 16 + 2 * tc - (tc & 1) + 2 * tile;
            int k0   = (lane & 3) * 2 + (r & 1) * 8;
            v[i] = packbf(wo[k0 * V_SZ + col], wo[(k0 + 1) * V_SZ + col]);
        }
        uint4* dst = reinterpret_cast<uint4*>(g_wt2 + t0);
#pragma unroll
        for (int i = 0; i < 4; i++)
            dst[i] = make_uint4(v[4 * i], v[4 * i + 1], v[4 * i + 2], v[4 * i + 3]);
    }
}

// -------- K2 fused (UNGATED): pass0 at full occupancy, tile-local gate, pass1 ---
// grid = 1024 (single co-resident wave: 32 regs, 0 smem, 256 thr -> 8 CTAs/SM).
// All blocks run pass0 concurrently (full-occupancy regime), then each tile's 16
// blocks proceed to stores as soon as THAT tile's sums are complete.
__global__ __launch_bounds__(256)
void k2f(float* __restrict__ out) {
    int blk  = blockIdx.x;
    int T    = blk >> 4;
    int bx   = blk & 15;
    int tid  = threadIdx.x;
    int w    = tid >> 5;
    int lane = tid & 31;
    int lq   = lane & 3;
    int m0   = T * MT;
    int wr0  = m0 + w * 16;
    int rA   = lane >> 2;
    int kc   = lq * 2;

    // A fragment, pre-scaled by log2(e): pass0 exp = ex2(d); pass1 logit = d*ln2
    const float* hA = g_h + (long)(wr0 + rA) * H_SZ;
    const float* hB = g_h + (long)(wr0 + rA + 8) * H_SZ;
    uint32_t a[4];
    a[0] = packbf(LOG2E * hA[kc],     LOG2E * hA[kc + 1]);
    a[1] = packbf(LOG2E * hB[kc],     LOG2E * hB[kc + 1]);
    a[2] = packbf(LOG2E * hA[kc + 8], LOG2E * hA[kc + 9]);
    a[3] = packbf(LOG2E * hB[kc + 8], LOG2E * hB[kc + 9]);

    const uint4* bptr = reinterpret_cast<const uint4*>(g_wt2) + (long)bx * NG * 32 + lane;
    long orowA = (long)(wr0 + rA) * V_SZ + bx * VR + 4 * lq;
    long orowB = orowA + 8L * V_SZ;

    // ---- pass 0: sum(exp) for chunk (bx, T) ----
    {
        float psA = 0.f, psB = 0.f;
#pragma unroll 5
        for (int g = 0; g < NG; g++) {
            uint4 b = bptr[(long)g * 32];
            float d0[4], d1[4];
            mma16816(d0, a, b.x, b.y);
            mma16816(d1, a, b.z, b.w);
            psA += ex2(d0[0]) + ex2(d0[1]) + ex2(d1[0]) + ex2(d1[1]);
            psB += ex2(d0[2]) + ex2(d0[3]) + ex2(d1[2]) + ex2(d1[3]);
        }
        psA += __shfl_xor_sync(0xffffffffu, psA, 1);
        psA += __shfl_xor_sync(0xffffffffu, psA, 2);
        psB += __shfl_xor_sync(0xffffffffu, psB, 1);
        psB += __shfl_xor_sync(0xffffffffu, psB, 2);
        if (lq == 0) {
            g_ps[(long)(wr0 + rA) * VSPLIT + bx]     = psA;
            g_ps[(long)(wr0 + rA + 8) * VSPLIT + bx] = psB;
        }
    }
    __threadfence();
    __syncthreads();
    if (tid == 0) atomicAdd((int*)&g_tdone[T], 1);

    // ---- tile gate: this tile's 16 chunks done (co-resident -> no deadlock) ----
    if (lane == 0) {
        while (g_tdone[T] < 16) __nanosleep(64);
    }
    __syncthreads();
    __threadfence();

    // lse per row
    float lseA, lseB;
    {
        const float4* pp = reinterpret_cast<const float4*>(g_ps + (long)(wr0 + rA) * VSPLIT);
        const float4* qq = reinterpret_cast<const float4*>(g_ps + (long)(wr0 + rA + 8) * VSPLIT);
        float sa = 0.f, sb = 0.f;
#pragma unroll
        for (int i = 0; i < VSPLIT / 4; i++) {
            float4 p = pp[i], q = qq[i];
            sa += (p.x + p.y) + (p.z + p.w);
            sb += (q.x + q.y) + (q.z + q.w);
        }
        lseA = __logf(sa);
        lseB = __logf(sb);
    }

    // ---- pass 1: store logit - lse  (logit = d * ln2) ----
#pragma unroll 5
    for (int g = 0; g < NG; g++) {
        uint4 b = bptr[(long)g * 32];
        float d0[4], d1[4];
        mma16816(d0, a, b.x, b.y);
        mma16816(d1, a, b.z, b.w);
        float4 vA = make_float4(fmaf(d0[0], LN2, -lseA), fmaf(d0[1], LN2, -lseA),
                                fmaf(d1[0], LN2, -lseA), fmaf(d1[1], LN2, -lseA));
        float4 vB = make_float4(fmaf(d0[2], LN2, -lseB), fmaf(d0[3], LN2, -lseB),
                                fmaf(d1[2], LN2, -lseB), fmaf(d1[3], LN2, -lseB));
        *reinterpret_cast<float4*>(out + orowA + g * 16) = vA;
        *reinterpret_cast<float4*>(out + orowB + g * 16) = vB;
    }
}

// -------- launch ----------------------------------------------------------------
extern "C" void kernel_launch(void* const* d_in, const int* in_sizes, int n_in,
                              void* d_out, int out_size) {
    const int*   input_batch = (const int*)d_in[0];
    const float* lookup      = (const float*)d_in[1];
    const float* weight_x    = (const float*)d_in[2];
    const float* weight_h    = (const float*)d_in[3];
    const float* weight_o    = (const float*)d_in[4];
    const float* h0          = (const float*)d_in[5];
    float*       out         = (float*)d_out;

    k_embed<<<(NROWS * H_SZ / 4) / 256, 256>>>(input_batch, lookup, weight_x);
    k_prep<<<96, 256>>>(weight_h, h0, weight_o);
    k2f<<<VSPLIT * NMT, 256>>>(out);
}